// round 13
// baseline (speedup 1.0000x reference)
#include <cuda_runtime.h>
#include <cuda_fp16.h>
#include <math.h>
#include <stdint.h>

#define Bb   2
#define Nn   2048
#define DIM  1024
#define Hh   16
#define DHd  64
#define Mrows (Bb * Nn)          // 4096
#define BHh  (Bb * Hh)           // 32
#define QMULT 0.18033688011112042f   // 0.125 * log2(e)

// fp16 scratch (device globals)
__device__ __half g_Xh[Mrows * DIM];
__device__ __half g_Wqkvh[3 * DIM * DIM];
__device__ __half g_Woh[DIM * DIM];
__device__ __half g_Qh[BHh * Nn * DHd];
__device__ __half g_Kh[BHh * Nn * DHd];
__device__ __half g_Vh[BHh * Nn * DHd];
__device__ __half g_AOh[Mrows * DIM];

// ---------------------------------------------------------------------------
__device__ __forceinline__ uint32_t cvta_s(const void* p) {
    return (uint32_t)__cvta_generic_to_shared(p);
}
__device__ __forceinline__ void ldsm4(uint32_t* r, uint32_t a) {
    asm volatile("ldmatrix.sync.aligned.m8n8.x4.shared.b16 {%0,%1,%2,%3}, [%4];"
                 : "=r"(r[0]), "=r"(r[1]), "=r"(r[2]), "=r"(r[3]) : "r"(a));
}
__device__ __forceinline__ void ldsm4t(uint32_t* r, uint32_t a) {
    asm volatile("ldmatrix.sync.aligned.m8n8.x4.trans.shared.b16 {%0,%1,%2,%3}, [%4];"
                 : "=r"(r[0]), "=r"(r[1]), "=r"(r[2]), "=r"(r[3]) : "r"(a));
}
__device__ __forceinline__ void mma16816(float* c, const uint32_t* a, const uint32_t* b) {
    asm volatile("mma.sync.aligned.m16n8k16.row.col.f32.f16.f16.f32 "
                 "{%0,%1,%2,%3}, {%4,%5,%6,%7}, {%8,%9}, {%0,%1,%2,%3};"
                 : "+f"(c[0]), "+f"(c[1]), "+f"(c[2]), "+f"(c[3])
                 : "r"(a[0]), "r"(a[1]), "r"(a[2]), "r"(a[3]), "r"(b[0]), "r"(b[1]));
}
__device__ __forceinline__ uint32_t pack_h2(float a, float b) {
    __half2 h = __floats2half2_rn(a, b);
    return *reinterpret_cast<uint32_t*>(&h);
}
__device__ __forceinline__ float ex2(float x) {
    float y;
    asm("ex2.approx.ftz.f32 %0, %1;" : "=f"(y) : "f"(x));
    return y;
}

#define CP16(dst, src) asm volatile("cp.async.cg.shared.global [%0], [%1], 16;" \
                                    :: "r"(dst), "l"(src))
#define CPCOMMIT() asm volatile("cp.async.commit_group;")
#define CPWAIT(N)  asm volatile("cp.async.wait_group %0;" :: "n"(N))

// ---------------------------------------------------------------------------
// merged fp32 -> fp16 conversion (unit = 8 floats)
// ---------------------------------------------------------------------------
__global__ __launch_bounds__(256)
void convert_all(const float* __restrict__ x,  const float* __restrict__ Wq,
                 const float* __restrict__ Wk, const float* __restrict__ Wv,
                 const float* __restrict__ Wo,
                 __half* __restrict__ Xh, __half* __restrict__ Wqkvh,
                 __half* __restrict__ Woh)
{
    int i = blockIdx.x * 256 + threadIdx.x;     // 0 .. 1048575
    const float* src;
    __half* dst;
    int j = i;
    if (j < 524288)      { src = x;  dst = Xh; }
    else {
        j -= 524288;
        if (j < 131072)      { src = Wq; dst = Wqkvh; }
        else { j -= 131072;
            if (j < 131072)  { src = Wk; dst = Wqkvh + 1048576; }
            else { j -= 131072;
                if (j < 131072) { src = Wv; dst = Wqkvh + 2097152; }
                else { j -= 131072; src = Wo; dst = Woh; }
            }
        }
    }
    float4 a = ((const float4*)src)[2 * j];
    float4 b = ((const float4*)src)[2 * j + 1];
    __half2 h[4] = { __floats2half2_rn(a.x, a.y), __floats2half2_rn(a.z, a.w),
                     __floats2half2_rn(b.x, b.y), __floats2half2_rn(b.z, b.w) };
    ((int4*)dst)[j] = *reinterpret_cast<int4*>(h);
}

// ---------------------------------------------------------------------------
// fp16 HMMA GEMM (round-9 best config, verbatim): CTA 128x128, BK=64,
// 3-stage cp.async, 8 warps 4(M)x2(N) warp tile 32x64, 2 CTAs/SM.
// EPI 0: fp32 out + bias. EPI 1: QKV demux + fused per-head L2 norm.
// ---------------------------------------------------------------------------
#define GSTG2 36864          // stage bytes: (128 A rows + 128 B rows) * 144

template <int EPI>
__global__ __launch_bounds__(256, 2)
void hgemm8(const __half* __restrict__ A, const __half* __restrict__ B,
            const float* __restrict__ bias, float* __restrict__ Cf,
            __half* __restrict__ Qo, __half* __restrict__ Ko, __half* __restrict__ Vo,
            const float* __restrict__ qsc, const float* __restrict__ ksc)
{
    extern __shared__ __align__(16) char gsm[];
    const uint32_t sb = cvta_s(gsm);

    const int tid = threadIdx.x;
    const int warp = tid >> 5, lane = tid & 31;
    const int bm = blockIdx.y * 128, bn = blockIdx.x * 128;
    const int wm = (warp >> 1) * 32, wn = (warp & 1) * 64;

    float c[2][8][4];
#pragma unroll
    for (int i = 0; i < 2; i++)
#pragma unroll
        for (int j = 0; j < 8; j++)
#pragma unroll
            for (int q = 0; q < 4; q++) c[i][j][q] = 0.0f;

#define GISSUE(S, KB)                                                          \
    do {                                                                       \
        uint32_t As_ = sb + (S) * GSTG2;                                       \
        uint32_t Bs_ = As_ + 18432;                                            \
        _Pragma("unroll")                                                      \
        for (int it = 0; it < 4; it++) {                                       \
            int id = it * 256 + tid;                                           \
            int m = id >> 3, c8 = id & 7;                                      \
            CP16(As_ + m * 144 + c8 * 16,                                      \
                 A + (size_t)(bm + m) * 1024 + (KB) + c8 * 8);                 \
            CP16(Bs_ + m * 144 + c8 * 16,                                      \
                 B + (size_t)(bn + m) * 1024 + (KB) + c8 * 8);                 \
        }                                                                      \
    } while (0)

    GISSUE(0, 0);  CPCOMMIT();
    GISSUE(1, 64); CPCOMMIT();

    for (int kt = 0; kt < 16; kt++) {
        if (kt < 15) CPWAIT(1); else CPWAIT(0);
        __syncthreads();     // stage kt ready; stage (kt+2)%3 drained by all warps

        if (kt + 2 < 16) { GISSUE((kt + 2) % 3, (kt + 2) * 64); CPCOMMIT(); }

        const uint32_t As = sb + (kt % 3) * GSTG2;
        const uint32_t Bs = As + 18432;

#pragma unroll
        for (int s = 0; s < 2; s++) {            // two k32 halves of BK=64
            uint32_t b[8][4];
#pragma unroll
            for (int in = 0; in < 8; in++)
                ldsm4(b[in], Bs + (wn + in * 8 + (lane & 7)) * 144
                               + s * 64 + (lane >> 3) * 16);
#pragma unroll
            for (int ks = 0; ks < 2; ks++) {
                uint32_t a[2][4];
#pragma unroll
                for (int im = 0; im < 2; im++)
                    ldsm4(a[im], As + (wm + im * 16 + (lane & 15)) * 144
                                   + s * 64 + ks * 32 + (lane >> 4) * 16);
#pragma unroll
                for (int im = 0; im < 2; im++)
#pragma unroll
                    for (int in = 0; in < 8; in++)
                        mma16816(c[im][in], a[im], &b[in][ks * 2]);
            }
        }
    }
#undef GISSUE

    // ---- epilogue ----
    const int r = lane >> 2, cq = (lane & 3) * 2;

    if (EPI == 0) {
        float2 bi[8];
#pragma unroll
        for (int in = 0; in < 8; in++)
            bi[in] = *(const float2*)&bias[bn + wn + in * 8 + cq];
#pragma unroll
        for (int im = 0; im < 2; im++)
#pragma unroll
            for (int hm = 0; hm < 2; hm++) {
                int m = bm + wm + im * 16 + hm * 8 + r;
#pragma unroll
                for (int in = 0; in < 8; in++) {
                    int e = bn + wn + in * 8 + cq;
                    *(float2*)&Cf[(size_t)m * 1024 + e] =
                        make_float2(c[im][in][hm * 2] + bi[in].x,
                                    c[im][in][hm * 2 + 1] + bi[in].y);
                }
            }
    } else {
        const int which = bn >> 10;                  // 0=Q 1=K 2=V
        const int bnl = bn & 1023;
        __half* dst = (which == 0) ? Qo : (which == 1) ? Ko : Vo;
        const int h = (bnl + wn) >> 6;               // warp N-tile = one head
        const float mult = (which == 0) ? QMULT : 1.0f;
        const float* sc = (which == 0) ? qsc : ksc;

        float2 s2[8];
        if (which < 2) {
#pragma unroll
            for (int in = 0; in < 8; in++)
                s2[in] = *(const float2*)&sc[h * 64 + in * 8 + cq];
        } else {
#pragma unroll
            for (int in = 0; in < 8; in++) s2[in] = make_float2(1.0f, 1.0f);
        }

#pragma unroll
        for (int im = 0; im < 2; im++)
#pragma unroll
            for (int hm = 0; hm < 2; hm++) {
                float inv = 1.0f;
                if (which < 2) {
                    float ss = 0.0f;
#pragma unroll
                    for (int in = 0; in < 8; in++)
                        ss += c[im][in][hm * 2] * c[im][in][hm * 2]
                            + c[im][in][hm * 2 + 1] * c[im][in][hm * 2 + 1];
                    ss += __shfl_xor_sync(0xffffffffu, ss, 1);
                    ss += __shfl_xor_sync(0xffffffffu, ss, 2);
                    inv = mult / fmaxf(sqrtf(ss), 1e-12f);
                }
                int m = bm + wm + im * 16 + hm * 8 + r;
                int bbq = m >> 11, n = m & 2047;
                __half* row = dst + (size_t)(((bbq * Hh + h) * Nn) + n) * DHd;
#pragma unroll
                for (int in = 0; in < 8; in++) {
                    int dh = in * 8 + cq;
                    *(__half2*)&row[dh] = __floats2half2_rn(
                        c[im][in][hm * 2] * inv * s2[in].x,
                        c[im][in][hm * 2 + 1] * inv * s2[in].y);
                }
            }
    }
}

// ---------------------------------------------------------------------------
// Flash attention with 128-KEY STAGES: 2-stage cp.async (36 KB/stage), each
// stage computed as two 64-key micro-tiles -> barriers/CPWAITs halved (16 vs
// 32). Inner compute identical to round 9: no online max (bounded base-2
// logits), per-thread row sums, hoisted Q frags, MUFU exp2.
// smem: Qs[128][72] + Ks[2][128][72] + Vs[2][128][72] = 92160 B, 2 CTAs/SM.
// ---------------------------------------------------------------------------
__global__ __launch_bounds__(256, 2)
void flash_h(const __half* __restrict__ Q, const __half* __restrict__ K,
             const __half* __restrict__ V, __half* __restrict__ Out)
{
    extern __shared__ __half fsm[];
    __half* Qs = fsm;                        // [128][72]
    __half* Ks = fsm + 128 * 72;             // [2][128][72]
    __half* Vs = Ks + 2 * 128 * 72;          // [2][128][72]

    const int tid = threadIdx.x;
    const int warp = tid >> 5, lane = tid & 31;
    const int bh = blockIdx.y;
    const int q0 = blockIdx.x * 128;
    const int b = bh >> 4, h = bh & 15;
    const int r = lane >> 2, cq = (lane & 3) * 2;

    const __half* Qg = Q + ((size_t)bh * Nn + q0) * DHd;
#pragma unroll
    for (int it = 0; it < 4; it++) {
        int id = it * 256 + tid;
        int m = id >> 3, cc = (id & 7) * 8;
        *(int4*)&Qs[m * 72 + cc] = *(const int4*)(Qg + m * DHd + cc);
    }

    const __half* Kg = K + (size_t)bh * Nn * DHd;
    const __half* Vg = V + (size_t)bh * Nn * DHd;

    // load one 128-key stage (K and V), 8 CP16/thread
#define ISSUEKV(S, KT)                                                         \
    do {                                                                       \
        _Pragma("unroll")                                                      \
        for (int i = 0; i < 4; i++) {                                          \
            int id = i * 256 + tid;                                            \
            int m = id >> 3, cc = (id & 7) * 8;                                \
            size_t go = (size_t)((KT) * 128 + m) * DHd + cc;                   \
            CP16(cvta_s(Ks + ((S) * 128 + m) * 72 + cc), Kg + go);             \
            CP16(cvta_s(Vs + ((S) * 128 + m) * 72 + cc), Vg + go);             \
        }                                                                      \
    } while (0)

    ISSUEKV(0, 0); CPCOMMIT();
    __syncthreads();                         // Qs visible

    uint32_t aq[4][4];                       // hoisted Q fragments
#pragma unroll
    for (int kq = 0; kq < 4; kq++)
        ldsm4(aq[kq], cvta_s(Qs + (warp * 16 + (lane & 15)) * 72
                                + kq * 16 + (lane >> 4) * 8));

    float O[8][4];
#pragma unroll
    for (int i = 0; i < 8; i++)
#pragma unroll
        for (int j = 0; j < 4; j++) O[i][j] = 0.0f;
    float l0 = 0.0f, l1 = 0.0f;              // per-thread partial row sums

    for (int kt = 0; kt < 16; kt++) {        // 16 stages of 128 keys
        CPWAIT(0);
        __syncthreads();                     // stage kt ready; other buf drained

        if (kt + 1 < 16) { ISSUEKV((kt + 1) & 1, kt + 1); CPCOMMIT(); }

#pragma unroll
        for (int half = 0; half < 2; half++) {     // two 64-key micro-tiles
            const int base = (kt & 1) * 128 + half * 64;

            float S[8][4];
#pragma unroll
            for (int i = 0; i < 8; i++)
#pragma unroll
                for (int j = 0; j < 4; j++) S[i][j] = 0.0f;

#pragma unroll
            for (int kh = 0; kh < 2; kh++) {
#pragma unroll
                for (int in = 0; in < 8; in++) {
                    uint32_t bk[4];
                    ldsm4(bk, cvta_s(Ks + (base + in * 8 + (lane & 7)) * 72
                                        + kh * 32 + (lane >> 3) * 8));
                    mma16816(S[in], aq[kh * 2],     &bk[0]);
                    mma16816(S[in], aq[kh * 2 + 1], &bk[2]);
                }
            }

            // p = 2^S (bounded, no max needed); per-thread row sums
#pragma unroll
            for (int in = 0; in < 8; in++) {
                S[in][0] = ex2(S[in][0]);
                S[in][1] = ex2(S[in][1]);
                S[in][2] = ex2(S[in][2]);
                S[in][3] = ex2(S[in][3]);
                l0 += S[in][0] + S[in][1];
                l1 += S[in][2] + S[in][3];
            }

            // O += P @ V
#pragma unroll
            for (int kj = 0; kj < 4; kj++) {
                uint32_t pa[4];
                pa[0] = pack_h2(S[2 * kj][0],     S[2 * kj][1]);
                pa[1] = pack_h2(S[2 * kj][2],     S[2 * kj][3]);
                pa[2] = pack_h2(S[2 * kj + 1][0], S[2 * kj + 1][1]);
                pa[3] = pack_h2(S[2 * kj + 1][2], S[2 * kj + 1][3]);
#pragma unroll
                for (int nv = 0; nv < 4; nv++) {
                    uint32_t bv[4];
                    ldsm4t(bv, cvta_s(Vs + (base + kj * 16 + ((lane >> 3) & 1) * 8
                                            + (lane & 7)) * 72
                                         + nv * 16 + (lane >> 4) * 8));
                    mma16816(O[nv * 2],     pa, &bv[0]);
                    mma16816(O[nv * 2 + 1], pa, &bv[2]);
                }
            }
        }
    }
#undef ISSUEKV

    // final row-sum reduce (4 lanes per row) + normalize + store
    l0 += __shfl_xor_sync(0xffffffffu, l0, 1);
    l0 += __shfl_xor_sync(0xffffffffu, l0, 2);
    l1 += __shfl_xor_sync(0xffffffffu, l1, 1);
    l1 += __shfl_xor_sync(0xffffffffu, l1, 2);
    float inv0 = 1.0f / l0, inv1 = 1.0f / l1;

    int nrow0 = q0 + warp * 16 + r;
    size_t base0 = ((size_t)b * Nn + nrow0) * DIM + h * DHd;
    size_t base1 = ((size_t)b * Nn + nrow0 + 8) * DIM + h * DHd;
#pragma unroll
    for (int nv = 0; nv < 8; nv++) {
        int col = nv * 8 + cq;
        *(__half2*)(Out + base0 + col) = __floats2half2_rn(O[nv][0] * inv0, O[nv][1] * inv0);
        *(__half2*)(Out + base1 + col) = __floats2half2_rn(O[nv][2] * inv1, O[nv][3] * inv1);
    }
}

// ---------------------------------------------------------------------------
extern "C" void kernel_launch(void* const* d_in, const int* in_sizes, int n_in,
                              void* d_out, int out_size)
{
    const float* x   = (const float*)d_in[0];
    const float* Wq  = (const float*)d_in[1];
    const float* Wk  = (const float*)d_in[2];
    const float* Wv  = (const float*)d_in[3];
    const float* Wo  = (const float*)d_in[4];
    const float* bo  = (const float*)d_in[5];
    const float* qsc = (const float*)d_in[6];
    const float* ksc = (const float*)d_in[7];
    float* out = (float*)d_out;

    __half *Xh, *Wqkvh, *Woh, *Qh, *Kh, *Vh, *AOh;
    cudaGetSymbolAddress((void**)&Xh,    g_Xh);
    cudaGetSymbolAddress((void**)&Wqkvh, g_Wqkvh);
    cudaGetSymbolAddress((void**)&Woh,   g_Woh);
    cudaGetSymbolAddress((void**)&Qh,    g_Qh);
    cudaGetSymbolAddress((void**)&Kh,    g_Kh);
    cudaGetSymbolAddress((void**)&Vh,    g_Vh);
    cudaGetSymbolAddress((void**)&AOh,   g_AOh);

    const int smem_g = 3 * GSTG2;                                   // 110592
    const int smem_f = (128 * 72 + 4 * 128 * 72) * sizeof(__half);  // 92160
    cudaFuncSetAttribute(hgemm8<0>, cudaFuncAttributeMaxDynamicSharedMemorySize, smem_g);
    cudaFuncSetAttribute(hgemm8<1>, cudaFuncAttributeMaxDynamicSharedMemorySize, smem_g);
    cudaFuncSetAttribute(flash_h,   cudaFuncAttributeMaxDynamicSharedMemorySize, smem_f);

    convert_all<<<4096, 256>>>(x, Wq, Wk, Wv, Wo, Xh, Wqkvh, Woh);

    // fused QKV projection + QK norm: N = 3072 in 128-wide tiles
    hgemm8<1><<<dim3(3 * DIM / 128, Mrows / 128), 256, smem_g>>>(
        Xh, Wqkvh, nullptr, nullptr, Qh, Kh, Vh, qsc, ksc);

    flash_h<<<dim3(Nn / 128, BHh), 256, smem_f>>>(Qh, Kh, Vh, AOh);

    // output projection
    hgemm8<0><<<dim3(DIM / 128, Mrows / 128), 256, smem_g>>>(
        AOh, Woh, bo, out, nullptr, nullptr, nullptr, nullptr, nullptr);
}

// round 16
// speedup vs baseline: 1.0254x; 1.0254x over previous
#include <cuda_runtime.h>
#include <cuda_fp16.h>
#include <math.h>
#include <stdint.h>

// Attention_45148696216391 — r16: r9 GEMMs + 4-stage flash K/V pipeline.
// (Re-issue of r14/r15 logic with fresh symbol names; prior two submissions
// died in the broker before compile.)

#define Bb   2
#define Nn   2048
#define DIM  1024
#define Hh   16
#define DHd  64
#define Mrows (Bb * Nn)          // 4096
#define BHh  (Bb * Hh)           // 32
#define QMULT 0.18033688011112042f   // 0.125 * log2(e)

// fp16 scratch (device globals)
__device__ __half s_Xh[Mrows * DIM];
__device__ __half s_Wqkvh[3 * DIM * DIM];
__device__ __half s_Woh[DIM * DIM];
__device__ __half s_Qh[BHh * Nn * DHd];
__device__ __half s_Kh[BHh * Nn * DHd];
__device__ __half s_Vh[BHh * Nn * DHd];
__device__ __half s_AOh[Mrows * DIM];

// ---------------------------------------------------------------------------
__device__ __forceinline__ uint32_t cvta_s(const void* p) {
    return (uint32_t)__cvta_generic_to_shared(p);
}
__device__ __forceinline__ void ldsm4(uint32_t* r, uint32_t a) {
    asm volatile("ldmatrix.sync.aligned.m8n8.x4.shared.b16 {%0,%1,%2,%3}, [%4];"
                 : "=r"(r[0]), "=r"(r[1]), "=r"(r[2]), "=r"(r[3]) : "r"(a));
}
__device__ __forceinline__ void ldsm4t(uint32_t* r, uint32_t a) {
    asm volatile("ldmatrix.sync.aligned.m8n8.x4.trans.shared.b16 {%0,%1,%2,%3}, [%4];"
                 : "=r"(r[0]), "=r"(r[1]), "=r"(r[2]), "=r"(r[3]) : "r"(a));
}
__device__ __forceinline__ void mma16816(float* c, const uint32_t* a, const uint32_t* b) {
    asm volatile("mma.sync.aligned.m16n8k16.row.col.f32.f16.f16.f32 "
                 "{%0,%1,%2,%3}, {%4,%5,%6,%7}, {%8,%9}, {%0,%1,%2,%3};"
                 : "+f"(c[0]), "+f"(c[1]), "+f"(c[2]), "+f"(c[3])
                 : "r"(a[0]), "r"(a[1]), "r"(a[2]), "r"(a[3]), "r"(b[0]), "r"(b[1]));
}
__device__ __forceinline__ uint32_t pack_h2(float a, float b) {
    __half2 h = __floats2half2_rn(a, b);
    return *reinterpret_cast<uint32_t*>(&h);
}
__device__ __forceinline__ float ex2(float x) {
    float y;
    asm("ex2.approx.ftz.f32 %0, %1;" : "=f"(y) : "f"(x));
    return y;
}

#define CP16(dst, src) asm volatile("cp.async.cg.shared.global [%0], [%1], 16;" \
                                    :: "r"(dst), "l"(src))
#define CPCOMMIT() asm volatile("cp.async.commit_group;")
#define CPWAIT(N)  asm volatile("cp.async.wait_group %0;" :: "n"(N))

// ---------------------------------------------------------------------------
// merged fp32 -> fp16 conversion (unit = 8 floats)
// ---------------------------------------------------------------------------
__global__ __launch_bounds__(256)
void cvt_all_k(const float* __restrict__ x,  const float* __restrict__ Wq,
               const float* __restrict__ Wk, const float* __restrict__ Wv,
               const float* __restrict__ Wo,
               __half* __restrict__ Xh, __half* __restrict__ Wqkvh,
               __half* __restrict__ Woh)
{
    int i = blockIdx.x * 256 + threadIdx.x;     // 0 .. 1048575
    const float* src;
    __half* dst;
    int j = i;
    if (j < 524288)      { src = x;  dst = Xh; }
    else {
        j -= 524288;
        if (j < 131072)      { src = Wq; dst = Wqkvh; }
        else { j -= 131072;
            if (j < 131072)  { src = Wk; dst = Wqkvh + 1048576; }
            else { j -= 131072;
                if (j < 131072) { src = Wv; dst = Wqkvh + 2097152; }
                else { j -= 131072; src = Wo; dst = Woh; }
            }
        }
    }
    float4 a = ((const float4*)src)[2 * j];
    float4 b = ((const float4*)src)[2 * j + 1];
    __half2 h[4] = { __floats2half2_rn(a.x, a.y), __floats2half2_rn(a.z, a.w),
                     __floats2half2_rn(b.x, b.y), __floats2half2_rn(b.z, b.w) };
    ((int4*)dst)[j] = *reinterpret_cast<int4*>(h);
}

// ---------------------------------------------------------------------------
// fp16 HMMA GEMM (round-9 best config): CTA 128x128, BK=64, 3-stage cp.async,
// 8 warps 4(M)x2(N) warp tile 32x64, 2 CTAs/SM.
// EPI 0: fp32 out + bias. EPI 1: QKV demux + fused per-head L2 norm.
// ---------------------------------------------------------------------------
#define GSTG2 36864          // stage bytes: (128 A rows + 128 B rows) * 144

template <int EPI>
__global__ __launch_bounds__(256, 2)
void hgemm10(const __half* __restrict__ A, const __half* __restrict__ B,
             const float* __restrict__ bias, float* __restrict__ Cf,
             __half* __restrict__ Qo, __half* __restrict__ Ko, __half* __restrict__ Vo,
             const float* __restrict__ qsc, const float* __restrict__ ksc)
{
    extern __shared__ __align__(16) char gsm[];
    const uint32_t sb = cvta_s(gsm);

    const int tid = threadIdx.x;
    const int warp = tid >> 5, lane = tid & 31;
    const int bm = blockIdx.y * 128, bn = blockIdx.x * 128;
    const int wm = (warp >> 1) * 32, wn = (warp & 1) * 64;

    float c[2][8][4];
#pragma unroll
    for (int i = 0; i < 2; i++)
#pragma unroll
        for (int j = 0; j < 8; j++)
#pragma unroll
            for (int q = 0; q < 4; q++) c[i][j][q] = 0.0f;

#define GISSUE(S, KB)                                                          \
    do {                                                                       \
        uint32_t As_ = sb + (S) * GSTG2;                                       \
        uint32_t Bs_ = As_ + 18432;                                            \
        _Pragma("unroll")                                                      \
        for (int it = 0; it < 4; it++) {                                       \
            int id = it * 256 + tid;                                           \
            int m = id >> 3, c8 = id & 7;                                      \
            CP16(As_ + m * 144 + c8 * 16,                                      \
                 A + (size_t)(bm + m) * 1024 + (KB) + c8 * 8);                 \
            CP16(Bs_ + m * 144 + c8 * 16,                                      \
                 B + (size_t)(bn + m) * 1024 + (KB) + c8 * 8);                 \
        }                                                                      \
    } while (0)

    GISSUE(0, 0);  CPCOMMIT();
    GISSUE(1, 64); CPCOMMIT();

    for (int kt = 0; kt < 16; kt++) {
        if (kt < 15) CPWAIT(1); else CPWAIT(0);
        __syncthreads();     // stage kt ready; stage (kt+2)%3 drained by all warps

        if (kt + 2 < 16) { GISSUE((kt + 2) % 3, (kt + 2) * 64); CPCOMMIT(); }

        const uint32_t As = sb + (kt % 3) * GSTG2;
        const uint32_t Bs = As + 18432;

#pragma unroll
        for (int s = 0; s < 2; s++) {            // two k32 halves of BK=64
            uint32_t b[8][4];
#pragma unroll
            for (int in = 0; in < 8; in++)
                ldsm4(b[in], Bs + (wn + in * 8 + (lane & 7)) * 144
                               + s * 64 + (lane >> 3) * 16);
#pragma unroll
            for (int ks = 0; ks < 2; ks++) {
                uint32_t a[2][4];
#pragma unroll
                for (int im = 0; im < 2; im++)
                    ldsm4(a[im], As + (wm + im * 16 + (lane & 15)) * 144
                                   + s * 64 + ks * 32 + (lane >> 4) * 16);
#pragma unroll
                for (int im = 0; im < 2; im++)
#pragma unroll
                    for (int in = 0; in < 8; in++)
                        mma16816(c[im][in], a[im], &b[in][ks * 2]);
            }
        }
    }
#undef GISSUE

    // ---- epilogue ----
    const int r = lane >> 2, cq = (lane & 3) * 2;

    if (EPI == 0) {
        float2 bi[8];
#pragma unroll
        for (int in = 0; in < 8; in++)
            bi[in] = *(const float2*)&bias[bn + wn + in * 8 + cq];
#pragma unroll
        for (int im = 0; im < 2; im++)
#pragma unroll
            for (int hm = 0; hm < 2; hm++) {
                int m = bm + wm + im * 16 + hm * 8 + r;
#pragma unroll
                for (int in = 0; in < 8; in++) {
                    int e = bn + wn + in * 8 + cq;
                    *(float2*)&Cf[(size_t)m * 1024 + e] =
                        make_float2(c[im][in][hm * 2] + bi[in].x,
                                    c[im][in][hm * 2 + 1] + bi[in].y);
                }
            }
    } else {
        const int which = bn >> 10;                  // 0=Q 1=K 2=V
        const int bnl = bn & 1023;
        __half* dst = (which == 0) ? Qo : (which == 1) ? Ko : Vo;
        const int h = (bnl + wn) >> 6;               // warp N-tile = one head
        const float mult = (which == 0) ? QMULT : 1.0f;
        const float* sc = (which == 0) ? qsc : ksc;

        float2 s2[8];
        if (which < 2) {
#pragma unroll
            for (int in = 0; in < 8; in++)
                s2[in] = *(const float2*)&sc[h * 64 + in * 8 + cq];
        } else {
#pragma unroll
            for (int in = 0; in < 8; in++) s2[in] = make_float2(1.0f, 1.0f);
        }

#pragma unroll
        for (int im = 0; im < 2; im++)
#pragma unroll
            for (int hm = 0; hm < 2; hm++) {
                float inv = 1.0f;
                if (which < 2) {
                    float ss = 0.0f;
#pragma unroll
                    for (int in = 0; in < 8; in++)
                        ss += c[im][in][hm * 2] * c[im][in][hm * 2]
                            + c[im][in][hm * 2 + 1] * c[im][in][hm * 2 + 1];
                    ss += __shfl_xor_sync(0xffffffffu, ss, 1);
                    ss += __shfl_xor_sync(0xffffffffu, ss, 2);
                    inv = mult / fmaxf(sqrtf(ss), 1e-12f);
                }
                int m = bm + wm + im * 16 + hm * 8 + r;
                int bbq = m >> 11, n = m & 2047;
                __half* row = dst + (size_t)(((bbq * Hh + h) * Nn) + n) * DHd;
#pragma unroll
                for (int in = 0; in < 8; in++) {
                    int dh = in * 8 + cq;
                    *(__half2*)&row[dh] = __floats2half2_rn(
                        c[im][in][hm * 2] * inv * s2[in].x,
                        c[im][in][hm * 2 + 1] * inv * s2[in].y);
                }
            }
    }
}

// ---------------------------------------------------------------------------
// Flash attention: round-9 structure, 4-stage K/V pipeline (load-ahead 3).
// 64-key tiles, no online max (bounded base-2 logits), per-thread row sums,
// hoisted Q frags, MUFU exp2.
// smem: Qs[128][72] + Ks[4][64][72] + Vs[4][64][72] = 92160 B, 2 CTAs/SM.
// ---------------------------------------------------------------------------
__global__ __launch_bounds__(256, 2)
void flash_p4(const __half* __restrict__ Q, const __half* __restrict__ K,
              const __half* __restrict__ V, __half* __restrict__ Out)
{
    extern __shared__ __half fsm[];
    __half* Qs = fsm;                        // [128][72]
    __half* Ks = fsm + 128 * 72;             // [4][64][72]
    __half* Vs = Ks + 4 * 64 * 72;           // [4][64][72]

    const int tid = threadIdx.x;
    const int warp = tid >> 5, lane = tid & 31;
    const int bh = blockIdx.y;
    const int q0 = blockIdx.x * 128;
    const int b = bh >> 4, h = bh & 15;
    const int r = lane >> 2, cq = (lane & 3) * 2;

    const __half* Qg = Q + ((size_t)bh * Nn + q0) * DHd;
#pragma unroll
    for (int it = 0; it < 4; it++) {
        int id = it * 256 + tid;
        int m = id >> 3, cc = (id & 7) * 8;
        *(int4*)&Qs[m * 72 + cc] = *(const int4*)(Qg + m * DHd + cc);
    }

    const __half* Kg = K + (size_t)bh * Nn * DHd;
    const __half* Vg = V + (size_t)bh * Nn * DHd;

#define ISSUEKV(S, KT)                                                         \
    do {                                                                       \
        _Pragma("unroll")                                                      \
        for (int i = 0; i < 2; i++) {                                          \
            int id = i * 256 + tid;                                            \
            int m = id >> 3, cc = (id & 7) * 8;                                \
            size_t go = (size_t)((KT) * 64 + m) * DHd + cc;                    \
            CP16(cvta_s(Ks + ((S) * 64 + m) * 72 + cc), Kg + go);              \
            CP16(cvta_s(Vs + ((S) * 64 + m) * 72 + cc), Vg + go);              \
        }                                                                      \
    } while (0)

    ISSUEKV(0, 0); CPCOMMIT();
    ISSUEKV(1, 1); CPCOMMIT();
    ISSUEKV(2, 2); CPCOMMIT();
    __syncthreads();                         // Qs visible

    uint32_t aq[4][4];                       // hoisted Q fragments
#pragma unroll
    for (int kq = 0; kq < 4; kq++)
        ldsm4(aq[kq], cvta_s(Qs + (warp * 16 + (lane & 15)) * 72
                                + kq * 16 + (lane >> 4) * 8));

    float O[8][4];
#pragma unroll
    for (int i = 0; i < 8; i++)
#pragma unroll
        for (int j = 0; j < 4; j++) O[i][j] = 0.0f;
    float l0 = 0.0f, l1 = 0.0f;              // per-thread partial row sums

    for (int kt = 0; kt < 32; kt++) {
        // in flight at top of iter: stages kt, kt+1, kt+2 (until tail)
        if (kt <= 29) CPWAIT(2);
        else if (kt == 30) CPWAIT(1);
        else CPWAIT(0);
        __syncthreads();     // stage kt ready; buffer (kt+3)%4 = (kt-1)%4 drained

        if (kt + 3 < 32) { ISSUEKV((kt + 3) & 3, kt + 3); CPCOMMIT(); }

        const int st = kt & 3;

        float S[8][4];
#pragma unroll
        for (int i = 0; i < 8; i++)
#pragma unroll
            for (int j = 0; j < 4; j++) S[i][j] = 0.0f;

#pragma unroll
        for (int kh = 0; kh < 2; kh++) {
#pragma unroll
            for (int in = 0; in < 8; in++) {
                uint32_t bk[4];
                ldsm4(bk, cvta_s(Ks + (st * 64 + in * 8 + (lane & 7)) * 72
                                    + kh * 32 + (lane >> 3) * 8));
                mma16816(S[in], aq[kh * 2],     &bk[0]);
                mma16816(S[in], aq[kh * 2 + 1], &bk[2]);
            }
        }

        // p = 2^S (bounded, no max needed); accumulate per-thread row sums
#pragma unroll
        for (int in = 0; in < 8; in++) {
            S[in][0] = ex2(S[in][0]);
            S[in][1] = ex2(S[in][1]);
            S[in][2] = ex2(S[in][2]);
            S[in][3] = ex2(S[in][3]);
            l0 += S[in][0] + S[in][1];
            l1 += S[in][2] + S[in][3];
        }

        // O += P @ V
#pragma unroll
        for (int kj = 0; kj < 4; kj++) {
            uint32_t pa[4];
            pa[0] = pack_h2(S[2 * kj][0],     S[2 * kj][1]);
            pa[1] = pack_h2(S[2 * kj][2],     S[2 * kj][3]);
            pa[2] = pack_h2(S[2 * kj + 1][0], S[2 * kj + 1][1]);
            pa[3] = pack_h2(S[2 * kj + 1][2], S[2 * kj + 1][3]);
#pragma unroll
            for (int nv = 0; nv < 4; nv++) {
                uint32_t bv[4];
                ldsm4t(bv, cvta_s(Vs + (st * 64 + kj * 16 + ((lane >> 3) & 1) * 8
                                        + (lane & 7)) * 72 + nv * 16 + (lane >> 4) * 8));
                mma16816(O[nv * 2],     pa, &bv[0]);
                mma16816(O[nv * 2 + 1], pa, &bv[2]);
            }
        }
    }
#undef ISSUEKV

    // final row-sum reduce (4 lanes per row) + normalize + store
    l0 += __shfl_xor_sync(0xffffffffu, l0, 1);
    l0 += __shfl_xor_sync(0xffffffffu, l0, 2);
    l1 += __shfl_xor_sync(0xffffffffu, l1, 1);
    l1 += __shfl_xor_sync(0xffffffffu, l1, 2);
    float inv0 = 1.0f / l0, inv1 = 1.0f / l1;

    int nrow0 = q0 + warp * 16 + r;
    size_t base0 = ((size_t)b * Nn + nrow0) * DIM + h * DHd;
    size_t base1 = ((size_t)b * Nn + nrow0 + 8) * DIM + h * DHd;
#pragma unroll
    for (int nv = 0; nv < 8; nv++) {
        int col = nv * 8 + cq;
        *(__half2*)(Out + base0 + col) = __floats2half2_rn(O[nv][0] * inv0, O[nv][1] * inv0);
        *(__half2*)(Out + base1 + col) = __floats2half2_rn(O[nv][2] * inv1, O[nv][3] * inv1);
    }
}

// ---------------------------------------------------------------------------
extern "C" void kernel_launch(void* const* d_in, const int* in_sizes, int n_in,
                              void* d_out, int out_size)
{
    const float* x   = (const float*)d_in[0];
    const float* Wq  = (const float*)d_in[1];
    const float* Wk  = (const float*)d_in[2];
    const float* Wv  = (const float*)d_in[3];
    const float* Wo  = (const float*)d_in[4];
    const float* bo  = (const float*)d_in[5];
    const float* qsc = (const float*)d_in[6];
    const float* ksc = (const float*)d_in[7];
    float* out = (float*)d_out;

    __half *Xh, *Wqkvh, *Woh, *Qh, *Kh, *Vh, *AOh;
    cudaGetSymbolAddress((void**)&Xh,    s_Xh);
    cudaGetSymbolAddress((void**)&Wqkvh, s_Wqkvh);
    cudaGetSymbolAddress((void**)&Woh,   s_Woh);
    cudaGetSymbolAddress((void**)&Qh,    s_Qh);
    cudaGetSymbolAddress((void**)&Kh,    s_Kh);
    cudaGetSymbolAddress((void**)&Vh,    s_Vh);
    cudaGetSymbolAddress((void**)&AOh,   s_AOh);

    const int smem_g = 3 * GSTG2;                                   // 110592
    const int smem_f = (128 * 72 + 8 * 64 * 72) * sizeof(__half);   // 92160
    cudaFuncSetAttribute(hgemm10<0>, cudaFuncAttributeMaxDynamicSharedMemorySize, smem_g);
    cudaFuncSetAttribute(hgemm10<1>, cudaFuncAttributeMaxDynamicSharedMemorySize, smem_g);
    cudaFuncSetAttribute(flash_p4,   cudaFuncAttributeMaxDynamicSharedMemorySize, smem_f);

    cvt_all_k<<<4096, 256>>>(x, Wq, Wk, Wv, Wo, Xh, Wqkvh, Woh);

    // fused QKV projection + QK norm: N = 3072 in 128-wide tiles
    hgemm10<1><<<dim3(3 * DIM / 128, Mrows / 128), 256, smem_g>>>(
        Xh, Wqkvh, nullptr, nullptr, Qh, Kh, Vh, qsc, ksc);

    flash_p4<<<dim3(Nn / 128, BHh), 256, smem_f>>>(Qh, Kh, Vh, AOh);

    // output projection
    hgemm10<0><<<dim3(DIM / 128, Mrows / 128), 256, smem_g>>>(
        AOh, Woh, bo, out, nullptr, nullptr, nullptr, nullptr, nullptr);
}